// round 16
// baseline (speedup 1.0000x reference)
#include <cuda_runtime.h>
#include <cstdint>

// Guided_Conv: 4096 independent 24x24x9 patches, persistent-CTA pipelined.
// patch n = b*256 + i*16 + j; output block at out + n*5184 (contiguous).
//
// R16 = R10 skeleton + cross-patch overlap:
//   5b executes on warps 0-7 + 17 (not warp 8), so group B (warps 8-16)
//   bar.arrive's past the post-5a barrier and runs patch i+1's phase 2
//   concurrently with patch i's 5b. w2p is double-buffered by parity.
//   Phase 5b itself is FROZEN in R10 form (R11/R12/R14 register-cliff evidence).

#define THREADS 576
#define GRID    444            // 148 SMs x 3 CTAs: exactly one wave
#define NPATCH  4096

// Padded pixel-major depth tile with zero halo (row stride 248 floats = 992 B).
// 248*3 == 8 (mod 32) -> depthwise-load banks (8*br+27*bc)%32 all distinct.
#define DROWP 248
#define DTILE_FLOATS (DROWP * 26)

#define FMA_F32X2(d, a, b, c) \
    asm("fma.rn.f32x2 %0, %1, %2, %3;" : "=l"(d) : "l"(a), "l"(b), "l"(c))

__device__ __forceinline__ uint32_t s2u(const void* p) {
    uint32_t a;
    asm("{ .reg .u64 t; cvta.to.shared.u64 t, %1; cvt.u32.u64 %0, t; }"
        : "=r"(a) : "l"(p));
    return a;
}

__device__ __forceinline__ void mbar_wait(uint32_t addr, uint32_t parity) {
    asm volatile(
        "{\n\t.reg .pred P;\n\t"
        "LW_%=:\n\t"
        "mbarrier.try_wait.parity.acquire.cta.shared::cta.b64 P, [%0], %1;\n\t"
        "@!P bra LW_%=;\n\t}"
        :: "r"(addr), "r"(parity) : "memory");
}

// Issue one 24-row tile load (20736 B) into smem via bulk-async, tx on mbar.
__device__ __forceinline__ void issue_tile(uint32_t mbar_a, uint32_t dst,
                                           uint32_t dst_stride, const char* src) {
    asm volatile("mbarrier.arrive.expect_tx.shared.b64 _, [%0], %1;"
                 :: "r"(mbar_a), "r"(20736u) : "memory");
    #pragma unroll 4
    for (int r = 0; r < 24; r++) {
        asm volatile(
            "cp.async.bulk.shared::cta.global.mbarrier::complete_tx::bytes "
            "[%0], [%1], %2, [%3];"
            :: "r"(dst + dst_stride * r), "l"(src + 13824ll * r), "r"(864u), "r"(mbar_a)
            : "memory");
    }
}

__device__ __forceinline__ const char* patch_src(const float* base, int n) {
    const int b  = n >> 8;
    const int pi = (n >> 4) & 15;
    const int pj = n & 15;
    const long long f = ((long long)(b * 384 + pi * 24) * 384 + pj * 24) * 9;
    return reinterpret_cast<const char*>(base + f);
}

__global__ __launch_bounds__(THREADS, 3)
void guided_conv_kernel(const float* __restrict__ guidance,
                        const float* __restrict__ depth,
                        const float* __restrict__ conv_w,   // (3,3,9,9)
                        const float* __restrict__ conv_b,   // (9,)
                        const float* __restrict__ dense_w,  // (9,81)
                        const float* __restrict__ dense_b,  // (81,)
                        float* __restrict__ out)
{
    __shared__ __align__(16) float g_s[2 * 5184];      // guidance -> dc -> output (per buf)
    __shared__ __align__(16) float d_s[DTILE_FLOATS];  // depth input tile (halo, input-only)
    __shared__ float cw_s[729];
    __shared__ float dw_s[729];
    __shared__ float cb_s[9];
    __shared__ float db_s[81];
    __shared__ float c_s[81];                          // conv out [k][o]
    __shared__ float part_s[243];                      // conv partials [r][k*9+o]
    __shared__ float gap_s[9];
    __shared__ float dvec_s[81];
    __shared__ float w1_s[81];
    __shared__ __align__(8) float w2p_s[2 * 90];       // mix, padded pairs [buf][ii][10]
    __shared__ __align__(8) uint64_t mbars[3];         // g0, g1, d

    const int tid = threadIdx.x;
    const uint32_t mbg0 = s2u(&mbars[0]);
    const uint32_t mbg1 = s2u(&mbars[1]);
    const uint32_t mbd  = s2u(&mbars[2]);
    const uint32_t gs_a = s2u(g_s);
    const uint32_t ds_a = s2u(d_s);

    const bool is_groupB = (tid >= 256) && (tid < 544);   // warps 8-16
    const bool in_5b     = (tid < 256) || (tid >= 544);   // warps 0-7 + 17

    // ================= Prologue (once per CTA) =================
    if (tid == 0) {
        asm volatile("mbarrier.init.shared.b64 [%0], 1;" :: "r"(mbg0) : "memory");
        asm volatile("mbarrier.init.shared.b64 [%0], 1;" :: "r"(mbg1) : "memory");
        asm volatile("mbarrier.init.shared.b64 [%0], 1;" :: "r"(mbd)  : "memory");
    }
    // zero depth-halo cells (900 floats): rows 0 & 25 + col slots 216..233 of rows 1..24
    for (int h = tid; h < 900; h += THREADS) {
        int addr;
        if (h < 234)      addr = h;
        else if (h < 468) addr = 6200 + (h - 234);
        else {
            const int z = h - 468;
            addr = DROWP * (z / 18 + 1) + 216 + (z % 18);
        }
        d_s[addr] = 0.f;
    }
    // weights (once per CTA)
    for (int idx = tid; idx < 729; idx += THREADS) {
        cw_s[idx] = conv_w[idx];
        dw_s[idx] = dense_w[idx];
    }
    if (tid < 81) db_s[tid] = dense_b[tid];
    if (tid >= 96 && tid < 105) cb_s[tid - 96] = conv_b[tid - 96];
    if (tid >= 112 && tid < 130) {                      // zero pad col of both w2p bufs
        const int z = tid - 112;
        w2p_s[(z / 9) * 90 + (z % 9) * 10 + 9] = 0.f;
    }
    __syncthreads();

    const int i0 = blockIdx.x;
    if (tid == 544) {
        issue_tile(mbg0, gs_a, 864u, patch_src(guidance, i0));       // g(patch0) -> g[0]
        issue_tile(mbd,  ds_a + 992u, 992u, patch_src(depth, i0));   // d(patch0)
    }

    // ================= Pipelined main loop =================
    int it = 0;
    for (int i = i0; i < NPATCH; i += GRID, ++it) {
        const int p = it & 1;
        float* gc = g_s + p * 5184;

        // -- step 1 (warp 17): after prior store drains, prefetch NEXT guidance --
        if (tid == 544) {
            asm volatile("cp.async.bulk.wait_group 0;" ::: "memory");
            if (i + GRID < NPATCH)
                issue_tile(p ? mbg0 : mbg1, gs_a + (1 - p) * 20736u, 864u,
                           patch_src(guidance, i + GRID));
        }

        // -- step 2: wait current guidance (parity closed-form) --
        mbar_wait(p ? mbg1 : mbg0, (uint32_t)((it >> 1) & 1));

        // -- phase 2: two independent weight chains on disjoint warp groups (R10 form) --
        if (tid < 256) {
            // warps 0-7: conv partials (243 thr) -> sum (81 thr) -> W1 norm (9 thr)
            if (tid < 243) {
                const int o  = tid % 9;
                const int k  = (tid / 9) % 9;
                const int r  = tid / 81;
                const int ky = k / 3, kx = k % 3;
                float acc = 0.f;
                #pragma unroll
                for (int s = 0; s < 3; s++) {
                    const float* gp = &gc[((8 * ky + r) * 24 + 8 * kx + s) * 9];
                    const float* wp = &cw_s[((r * 3 + s) * 9) * 9 + o];
                    #pragma unroll
                    for (int ii = 0; ii < 9; ii++)
                        acc += gp[ii] * wp[ii * 9];
                }
                part_s[r * 81 + k * 9 + o] = acc;
            }
            asm volatile("bar.sync 1, 256;" ::: "memory");
            if (tid < 81)
                c_s[tid] = cb_s[tid % 9] + part_s[tid] + part_s[81 + tid] + part_s[162 + tid];
            asm volatile("bar.sync 1, 256;" ::: "memory");
            if (tid < 9) {
                const int o = tid;
                float ss = 0.f;
                #pragma unroll
                for (int k = 0; k < 9; k++) { const float v = c_s[k * 9 + o]; ss += v * v; }
                const float scale = 1.0f / fmaxf(sqrtf(ss), 1.0f);
                #pragma unroll
                for (int k = 0; k < 9; k++) w1_s[k * 9 + o] = c_s[k * 9 + o] * scale;
            }
        } else if (tid < 544) {
            // warps 8-16: patch mean -> dense -> W2 clip-by-norm (writes w2p buf p)
            {
                const int f    = (tid - 256) >> 5;
                const int lane = tid & 31;
                float s = 0.f;
                #pragma unroll
                for (int pp = 0; pp < 18; pp++)
                    s += gc[(lane + 32 * pp) * 9 + f];   // stride 9 -> conflict-free
                #pragma unroll
                for (int off = 16; off > 0; off >>= 1)
                    s += __shfl_down_sync(0xffffffffu, s, off);
                if (lane == 0) gap_s[f] = s * (1.0f / 576.0f);
            }
            asm volatile("bar.sync 2, 288;" ::: "memory");
            if (tid < 337) {
                const int j = tid - 256;
                float acc = db_s[j];
                #pragma unroll
                for (int ii = 0; ii < 9; ii++)
                    acc += gap_s[ii] * dw_s[ii * 81 + j];
                dvec_s[j] = acc;
            }
            asm volatile("bar.sync 2, 288;" ::: "memory");
            if (tid < 265) {
                const int o = tid - 256;
                float ss = 0.f;
                #pragma unroll
                for (int ii = 0; ii < 9; ii++) { const float v = dvec_s[ii * 9 + o]; ss += v * v; }
                const float scale = 1.0f / fmaxf(sqrtf(ss), 1.0f);
                #pragma unroll
                for (int ii = 0; ii < 9; ii++)
                    w2p_s[p * 90 + ii * 10 + o] = dvec_s[ii * 9 + o] * scale;
            }
        }
        __syncthreads();

        // -- step 4: wait current depth input --
        mbar_wait(mbd, (uint32_t)(it & 1));

        // -- phase 5a: per-channel depthwise 3x3; dc overwrites gc (guidance dead) --
        {
            const int f   = tid >> 6;
            const int blk = tid & 63;
            const int br  = blk >> 3;
            const int bc  = blk & 7;
            const float* dbase = d_s + f + 744 * br;          // 248*3
            const int q0 = 27 * bc - 9;
            const float* pA = dbase + ((bc == 0) ? 225 : q0); // left col (halo wraps)
            const float* pB = dbase + q0;

            float w1f[9];
            #pragma unroll
            for (int k = 0; k < 9; k++) w1f[k] = w1_s[k * 9 + f];

            float win[15];
            #pragma unroll
            for (int r = 0; r < 3; r++) {
                win[r * 5 + 0] = pA[DROWP * r];
                #pragma unroll
                for (int c = 1; c < 5; c++)
                    win[r * 5 + c] = pB[DROWP * r + 9 * c];
            }

            #pragma unroll
            for (int rp = 0; rp < 3; rp++) {
                #pragma unroll
                for (int cp = 0; cp < 3; cp++) {
                    float acc = 0.f;
                    #pragma unroll
                    for (int dy = 0; dy < 3; dy++)
                        #pragma unroll
                        for (int dx = 0; dx < 3; dx++)
                            acc += w1f[dy * 3 + dx] * win[dy * 5 + cp + dx];
                    const int pix = (3 * br + rp) * 24 + 3 * bc + cp;
                    gc[pix * 9 + f] = acc;                    // conflict-free
                }
                if (rp < 2) {
                    #pragma unroll
                    for (int ii = 0; ii < 10; ii++) win[ii] = win[ii + 5];
                    win[10] = pA[DROWP * (rp + 3)];
                    #pragma unroll
                    for (int c = 1; c < 5; c++)
                        win[10 + c] = pB[DROWP * (rp + 3) + 9 * c];
                }
            }
        }

        // -- post-5a barrier (asymmetric): group B arrives and runs ahead to
        //    patch i+1's phase 2, overlapping with 5b of patch i --
        if (is_groupB) {
            asm volatile("bar.arrive 4, 576;" ::: "memory");
            continue;   // re-converges at the post-phase-2 __syncthreads of i+1
        }
        asm volatile("bar.sync 4, 576;" ::: "memory");

        // -- step 6 (warp 17): depth consumed -> prefetch NEXT depth --
        if (tid == 544 && i + GRID < NPATCH)
            issue_tile(mbd, ds_a + 992u, 992u, patch_src(depth, i + GRID));

        // -- phase 5b: 9x9 mix IN-PLACE in gc (EXACT R10 form — FROZEN),
        //    executed by warps 0-7 + warp 17 (t in [0,288)) --
        {
            const int t = (tid < 256) ? tid : (tid - 288);    // warp 17 -> 256..287
            float* dca = &gc[t * 9];
            float* dcb = &gc[(t + 288) * 9];

            uint64_t acc_a[5], acc_b[5];
            #pragma unroll
            for (int j = 0; j < 5; j++) { acc_a[j] = 0ull; acc_b[j] = 0ull; }

            float va[9], vb[9];
            #pragma unroll
            for (int ii = 0; ii < 9; ii++) { va[ii] = dca[ii]; vb[ii] = dcb[ii]; }

            #pragma unroll
            for (int ii = 0; ii < 9; ii++) {
                uint64_t sa, sb;
                const uint32_t xa = __float_as_uint(va[ii]);
                const uint32_t xb = __float_as_uint(vb[ii]);
                asm("mov.b64 %0, {%1, %1};" : "=l"(sa) : "r"(xa));
                asm("mov.b64 %0, {%1, %1};" : "=l"(sb) : "r"(xb));
                const uint64_t* w2row =
                    reinterpret_cast<const uint64_t*>(&w2p_s[p * 90 + ii * 10]);
                #pragma unroll
                for (int j = 0; j < 5; j++) {
                    const uint64_t w2v = w2row[j];            // LDS.64 broadcast
                    FMA_F32X2(acc_a[j], sa, w2v, acc_a[j]);
                    FMA_F32X2(acc_b[j], sb, w2v, acc_b[j]);
                }
            }

            #pragma unroll
            for (int j = 0; j < 4; j++) {
                dca[2 * j]     = __uint_as_float((uint32_t)acc_a[j]);
                dca[2 * j + 1] = __uint_as_float((uint32_t)(acc_a[j] >> 32));
                dcb[2 * j]     = __uint_as_float((uint32_t)acc_b[j]);
                dcb[2 * j + 1] = __uint_as_float((uint32_t)(acc_b[j] >> 32));
            }
            dca[8] = __uint_as_float((uint32_t)acc_a[4]);
            dcb[8] = __uint_as_float((uint32_t)acc_b[4]);
        }

        // -- post-5b producer/consumer barrier: warps 0-7 arrive, warp 17 syncs --
        if (tid < 256) {
            asm volatile("bar.arrive 5, 288;" ::: "memory");
        } else {
            asm volatile("bar.sync 5, 288;" ::: "memory");
            // -- step 8 (warp 17): bulk-store the patch; wait deferred to step 1 --
            if (tid == 544) {
                asm volatile("fence.proxy.async;" ::: "memory");
                asm volatile(
                    "cp.async.bulk.global.shared::cta.bulk_group [%0], [%1], %2;"
                    :: "l"(out + (size_t)i * 5184), "r"(gs_a + p * 20736u), "r"(20736u)
                    : "memory");
                asm volatile("cp.async.bulk.commit_group;" ::: "memory");
            }
        }
    }

    // drain the final output store before CTA retirement
    if (tid == 544)
        asm volatile("cp.async.bulk.wait_group 0;" ::: "memory");
}

extern "C" void kernel_launch(void* const* d_in, const int* in_sizes, int n_in,
                              void* d_out, int out_size) {
    const float* guidance = (const float*)d_in[0];
    const float* depth    = (const float*)d_in[1];
    const float* conv_w   = (const float*)d_in[2];
    const float* conv_b   = (const float*)d_in[3];
    const float* dense_w  = (const float*)d_in[4];
    const float* dense_b  = (const float*)d_in[5];
    float* out = (float*)d_out;

    guided_conv_kernel<<<GRID, THREADS>>>(guidance, depth, conv_w, conv_b,
                                          dense_w, dense_b, out);
}

// round 17
// speedup vs baseline: 1.4364x; 1.4364x over previous
#include <cuda_runtime.h>
#include <cstdint>

// Guided_Conv: 4096 independent 24x24x9 patches, persistent-CTA pipelined.
// patch n = b*256 + i*16 + j; output block at out + n*5184 (contiguous).
//
// FINAL (== R10, the measured optimum at 60.2us):
//  - persistent 444 CTAs (148 SM x 3), one wave; weights loaded once per CTA
//  - inputs via cp.async.bulk + mbarrier (double-buffered guidance, prefetch
//    one full iteration ahead; depth prefetched right after 5a consumes it)
//  - guidance buffer reused in-place: guidance -> dc -> output staging
//  - conflict-free pixel-major depth tile with wrapped zero halo (DROWP=248)
//  - phase 5b: packed f32x2 FMAs, interleaved single-LDS.64 w2 broadcasts
//    (R11/R12/R14/R16 all showed any widening/restructure trips the register
//    cliff into L2 spill; this exact form is the stable point)
//  - output via single 20736B cp.async.bulk store, wait deferred one iteration

#define THREADS 576
#define GRID    444            // 148 SMs x 3 CTAs: exactly one wave
#define NPATCH  4096

// Padded pixel-major depth tile with zero halo (row stride 248 floats = 992 B).
// 248*3 == 8 (mod 32) -> depthwise-load banks (8*br+27*bc)%32 all distinct.
#define DROWP 248
#define DTILE_FLOATS (DROWP * 26)

#define FMA_F32X2(d, a, b, c) \
    asm("fma.rn.f32x2 %0, %1, %2, %3;" : "=l"(d) : "l"(a), "l"(b), "l"(c))

__device__ __forceinline__ uint32_t s2u(const void* p) {
    uint32_t a;
    asm("{ .reg .u64 t; cvta.to.shared.u64 t, %1; cvt.u32.u64 %0, t; }"
        : "=r"(a) : "l"(p));
    return a;
}

__device__ __forceinline__ void mbar_wait(uint32_t addr, uint32_t parity) {
    asm volatile(
        "{\n\t.reg .pred P;\n\t"
        "LW_%=:\n\t"
        "mbarrier.try_wait.parity.acquire.cta.shared::cta.b64 P, [%0], %1;\n\t"
        "@!P bra LW_%=;\n\t}"
        :: "r"(addr), "r"(parity) : "memory");
}

// Issue one 24-row tile load (20736 B) into smem via bulk-async, tx on mbar.
__device__ __forceinline__ void issue_tile(uint32_t mbar_a, uint32_t dst,
                                           uint32_t dst_stride, const char* src) {
    asm volatile("mbarrier.arrive.expect_tx.shared.b64 _, [%0], %1;"
                 :: "r"(mbar_a), "r"(20736u) : "memory");
    #pragma unroll 4
    for (int r = 0; r < 24; r++) {
        asm volatile(
            "cp.async.bulk.shared::cta.global.mbarrier::complete_tx::bytes "
            "[%0], [%1], %2, [%3];"
            :: "r"(dst + dst_stride * r), "l"(src + 13824ll * r), "r"(864u), "r"(mbar_a)
            : "memory");
    }
}

__device__ __forceinline__ const char* patch_src(const float* base, int n) {
    const int b  = n >> 8;
    const int pi = (n >> 4) & 15;
    const int pj = n & 15;
    const long long f = ((long long)(b * 384 + pi * 24) * 384 + pj * 24) * 9;
    return reinterpret_cast<const char*>(base + f);
}

__global__ __launch_bounds__(THREADS, 3)
void guided_conv_kernel(const float* __restrict__ guidance,
                        const float* __restrict__ depth,
                        const float* __restrict__ conv_w,   // (3,3,9,9)
                        const float* __restrict__ conv_b,   // (9,)
                        const float* __restrict__ dense_w,  // (9,81)
                        const float* __restrict__ dense_b,  // (81,)
                        float* __restrict__ out)
{
    __shared__ __align__(16) float g_s[2 * 5184];      // guidance -> dc -> output (per buf)
    __shared__ __align__(16) float d_s[DTILE_FLOATS];  // depth input tile (halo, input-only)
    __shared__ float cw_s[729];
    __shared__ float dw_s[729];
    __shared__ float cb_s[9];
    __shared__ float db_s[81];
    __shared__ float c_s[81];                          // conv out [k][o]
    __shared__ float part_s[243];                      // conv partials [r][k*9+o]
    __shared__ float gap_s[9];
    __shared__ float dvec_s[81];
    __shared__ float w1_s[81];
    __shared__ __align__(8) float w2p_s[90];           // mix, padded pairs [ii][10]
    __shared__ __align__(8) uint64_t mbars[3];         // g0, g1, d

    const int tid = threadIdx.x;
    const uint32_t mbg0 = s2u(&mbars[0]);
    const uint32_t mbg1 = s2u(&mbars[1]);
    const uint32_t mbd  = s2u(&mbars[2]);
    const uint32_t gs_a = s2u(g_s);
    const uint32_t ds_a = s2u(d_s);

    // ================= Prologue (once per CTA) =================
    if (tid == 0) {
        asm volatile("mbarrier.init.shared.b64 [%0], 1;" :: "r"(mbg0) : "memory");
        asm volatile("mbarrier.init.shared.b64 [%0], 1;" :: "r"(mbg1) : "memory");
        asm volatile("mbarrier.init.shared.b64 [%0], 1;" :: "r"(mbd)  : "memory");
    }
    // zero depth-halo cells (900 floats): rows 0 & 25 + col slots 216..233 of rows 1..24
    for (int h = tid; h < 900; h += THREADS) {
        int addr;
        if (h < 234)      addr = h;
        else if (h < 468) addr = 6200 + (h - 234);
        else {
            const int z = h - 468;
            addr = DROWP * (z / 18 + 1) + 216 + (z % 18);
        }
        d_s[addr] = 0.f;
    }
    // weights (once per CTA)
    for (int idx = tid; idx < 729; idx += THREADS) {
        cw_s[idx] = conv_w[idx];
        dw_s[idx] = dense_w[idx];
    }
    if (tid < 81) db_s[tid] = dense_b[tid];
    if (tid >= 96 && tid < 105) cb_s[tid - 96] = conv_b[tid - 96];
    if (tid >= 112 && tid < 121) w2p_s[(tid - 112) * 10 + 9] = 0.f;   // pad column
    __syncthreads();

    const int i0 = blockIdx.x;
    if (tid == 544) {
        issue_tile(mbg0, gs_a, 864u, patch_src(guidance, i0));       // g(patch0) -> g[0]
        issue_tile(mbd,  ds_a + 992u, 992u, patch_src(depth, i0));   // d(patch0)
    }

    // ================= Pipelined main loop =================
    int it = 0;
    for (int i = i0; i < NPATCH; i += GRID, ++it) {
        const int p = it & 1;
        float* gc = g_s + p * 5184;

        // -- step 1 (warp 17): after prior store drains, prefetch NEXT guidance --
        if (tid == 544) {
            asm volatile("cp.async.bulk.wait_group 0;" ::: "memory");
            if (i + GRID < NPATCH)
                issue_tile(p ? mbg0 : mbg1, gs_a + (1 - p) * 20736u, 864u,
                           patch_src(guidance, i + GRID));
        }

        // -- step 2: wait current guidance (parity closed-form) --
        mbar_wait(p ? mbg1 : mbg0, (uint32_t)((it >> 1) & 1));

        // -- phase 2: two independent weight chains on disjoint warp groups --
        if (tid < 256) {
            // warps 0-7: conv partials (243 thr) -> sum (81 thr) -> W1 norm (9 thr)
            if (tid < 243) {
                const int o  = tid % 9;
                const int k  = (tid / 9) % 9;
                const int r  = tid / 81;
                const int ky = k / 3, kx = k % 3;
                float acc = 0.f;
                #pragma unroll
                for (int s = 0; s < 3; s++) {
                    const float* gp = &gc[((8 * ky + r) * 24 + 8 * kx + s) * 9];
                    const float* wp = &cw_s[((r * 3 + s) * 9) * 9 + o];
                    #pragma unroll
                    for (int ii = 0; ii < 9; ii++)
                        acc += gp[ii] * wp[ii * 9];
                }
                part_s[r * 81 + k * 9 + o] = acc;
            }
            asm volatile("bar.sync 1, 256;" ::: "memory");
            if (tid < 81)
                c_s[tid] = cb_s[tid % 9] + part_s[tid] + part_s[81 + tid] + part_s[162 + tid];
            asm volatile("bar.sync 1, 256;" ::: "memory");
            if (tid < 9) {
                const int o = tid;
                float ss = 0.f;
                #pragma unroll
                for (int k = 0; k < 9; k++) { const float v = c_s[k * 9 + o]; ss += v * v; }
                const float scale = 1.0f / fmaxf(sqrtf(ss), 1.0f);
                #pragma unroll
                for (int k = 0; k < 9; k++) w1_s[k * 9 + o] = c_s[k * 9 + o] * scale;
            }
        } else if (tid < 544) {
            // warps 8-16: patch mean -> dense -> W2 clip-by-norm (paired layout)
            {
                const int f    = (tid - 256) >> 5;
                const int lane = tid & 31;
                float s = 0.f;
                #pragma unroll
                for (int pp = 0; pp < 18; pp++)
                    s += gc[(lane + 32 * pp) * 9 + f];   // stride 9 -> conflict-free
                #pragma unroll
                for (int off = 16; off > 0; off >>= 1)
                    s += __shfl_down_sync(0xffffffffu, s, off);
                if (lane == 0) gap_s[f] = s * (1.0f / 576.0f);
            }
            asm volatile("bar.sync 2, 288;" ::: "memory");
            if (tid < 337) {
                const int j = tid - 256;
                float acc = db_s[j];
                #pragma unroll
                for (int ii = 0; ii < 9; ii++)
                    acc += gap_s[ii] * dw_s[ii * 81 + j];
                dvec_s[j] = acc;
            }
            asm volatile("bar.sync 2, 288;" ::: "memory");
            if (tid < 265) {
                const int o = tid - 256;
                float ss = 0.f;
                #pragma unroll
                for (int ii = 0; ii < 9; ii++) { const float v = dvec_s[ii * 9 + o]; ss += v * v; }
                const float scale = 1.0f / fmaxf(sqrtf(ss), 1.0f);
                #pragma unroll
                for (int ii = 0; ii < 9; ii++) w2p_s[ii * 10 + o] = dvec_s[ii * 9 + o] * scale;
            }
        }
        __syncthreads();

        // -- step 4: wait current depth input --
        mbar_wait(mbd, (uint32_t)(it & 1));

        // -- phase 5a: per-channel depthwise 3x3; dc overwrites gc (guidance dead) --
        {
            const int f   = tid >> 6;
            const int blk = tid & 63;
            const int br  = blk >> 3;
            const int bc  = blk & 7;
            const float* dbase = d_s + f + 744 * br;          // 248*3
            const int q0 = 27 * bc - 9;
            const float* pA = dbase + ((bc == 0) ? 225 : q0); // left col (halo wraps)
            const float* pB = dbase + q0;

            float w1f[9];
            #pragma unroll
            for (int k = 0; k < 9; k++) w1f[k] = w1_s[k * 9 + f];

            float win[15];
            #pragma unroll
            for (int r = 0; r < 3; r++) {
                win[r * 5 + 0] = pA[DROWP * r];
                #pragma unroll
                for (int c = 1; c < 5; c++)
                    win[r * 5 + c] = pB[DROWP * r + 9 * c];
            }

            #pragma unroll
            for (int rp = 0; rp < 3; rp++) {
                #pragma unroll
                for (int cp = 0; cp < 3; cp++) {
                    float acc = 0.f;
                    #pragma unroll
                    for (int dy = 0; dy < 3; dy++)
                        #pragma unroll
                        for (int dx = 0; dx < 3; dx++)
                            acc += w1f[dy * 3 + dx] * win[dy * 5 + cp + dx];
                    const int pix = (3 * br + rp) * 24 + 3 * bc + cp;
                    gc[pix * 9 + f] = acc;                    // conflict-free
                }
                if (rp < 2) {
                    #pragma unroll
                    for (int ii = 0; ii < 10; ii++) win[ii] = win[ii + 5];
                    win[10] = pA[DROWP * (rp + 3)];
                    #pragma unroll
                    for (int c = 1; c < 5; c++)
                        win[10 + c] = pB[DROWP * (rp + 3) + 9 * c];
                }
            }
        }
        __syncthreads();

        // -- step 6 (warp 17): depth consumed -> prefetch NEXT depth --
        if (tid == 544 && i + GRID < NPATCH)
            issue_tile(mbd, ds_a + 992u, 992u, patch_src(depth, i + GRID));

        // -- phase 5b: 9x9 mix IN-PLACE in gc (packed f32x2, 2 px/thread) --
        if (tid < 288) {
            float* dca = &gc[tid * 9];
            float* dcb = &gc[(tid + 288) * 9];

            uint64_t acc_a[5], acc_b[5];
            #pragma unroll
            for (int j = 0; j < 5; j++) { acc_a[j] = 0ull; acc_b[j] = 0ull; }

            float va[9], vb[9];
            #pragma unroll
            for (int ii = 0; ii < 9; ii++) { va[ii] = dca[ii]; vb[ii] = dcb[ii]; }

            #pragma unroll
            for (int ii = 0; ii < 9; ii++) {
                uint64_t sa, sb;
                const uint32_t xa = __float_as_uint(va[ii]);
                const uint32_t xb = __float_as_uint(vb[ii]);
                asm("mov.b64 %0, {%1, %1};" : "=l"(sa) : "r"(xa));
                asm("mov.b64 %0, {%1, %1};" : "=l"(sb) : "r"(xb));
                const uint64_t* w2row = reinterpret_cast<const uint64_t*>(&w2p_s[ii * 10]);
                #pragma unroll
                for (int j = 0; j < 5; j++) {
                    const uint64_t w2v = w2row[j];            // LDS.64 broadcast
                    FMA_F32X2(acc_a[j], sa, w2v, acc_a[j]);
                    FMA_F32X2(acc_b[j], sb, w2v, acc_b[j]);
                }
            }

            #pragma unroll
            for (int j = 0; j < 4; j++) {
                dca[2 * j]     = __uint_as_float((uint32_t)acc_a[j]);
                dca[2 * j + 1] = __uint_as_float((uint32_t)(acc_a[j] >> 32));
                dcb[2 * j]     = __uint_as_float((uint32_t)acc_b[j]);
                dcb[2 * j + 1] = __uint_as_float((uint32_t)(acc_b[j] >> 32));
            }
            dca[8] = __uint_as_float((uint32_t)acc_a[4]);
            dcb[8] = __uint_as_float((uint32_t)acc_b[4]);
        }
        __syncthreads();

        // -- step 8 (warp 17): bulk-store the patch from gc; wait deferred to step 1 --
        if (tid == 544) {
            asm volatile("fence.proxy.async;" ::: "memory");
            asm volatile(
                "cp.async.bulk.global.shared::cta.bulk_group [%0], [%1], %2;"
                :: "l"(out + (size_t)i * 5184), "r"(gs_a + p * 20736u), "r"(20736u)
                : "memory");
            asm volatile("cp.async.bulk.commit_group;" ::: "memory");
        }
    }

    // drain the final output store before CTA retirement
    if (tid == 544)
        asm volatile("cp.async.bulk.wait_group 0;" ::: "memory");
}

extern "C" void kernel_launch(void* const* d_in, const int* in_sizes, int n_in,
                              void* d_out, int out_size) {
    const float* guidance = (const float*)d_in[0];
    const float* depth    = (const float*)d_in[1];
    const float* conv_w   = (const float*)d_in[2];
    const float* conv_b   = (const float*)d_in[3];
    const float* dense_w  = (const float*)d_in[4];
    const float* dense_b  = (const float*)d_in[5];
    float* out = (float*)d_out;

    guided_conv_kernel<<<GRID, THREADS>>>(guidance, depth, conv_w, conv_b,
                                          dense_w, dense_b, out);
}